// round 6
// baseline (speedup 1.0000x reference)
#include <cuda_runtime.h>
#include <math.h>

#define BN   4
#define NG   16
#define NP   64
#define SZ   32
#define HH   640
#define WW   640
#define NPIX 1024
#define NBOX 80
#define NPAIR 4096            // BN*NG*NP
#define C1V  6.5025f
#define C2V  58.5225f
#define THRESH 0.3f
#define PX   49               // x-padded pitch (8 left pad), odd -> conflict-free
#define PY   45               // y-padded pitch (5 top pad), odd -> conflict-free
#define GRID 592              // 148 SMs * 4 resident blocks
#define MAXITEMS 3*NPAIR      // 12288 channel-items max
#define MAXLOCAL 24           // ceil(12288/592)=21, +margin

// Normalized 11-tap Gaussian (sigma=1.5)
__constant__ float GK[11] = {
    0.00102838f, 0.00759870f, 0.03600077f, 0.10936100f, 0.21300570f,
    0.26601172f,
    0.21300570f, 0.10936100f, 0.03600077f, 0.00759870f, 0.00102838f
};

// Globals (zero-initialized; d_done reset by last block each run)
__device__ float d_v_ssim[MAXITEMS];
__device__ float d_v_l1  [MAXITEMS];
__device__ unsigned int d_done;

__global__ __launch_bounds__(256, 4)
void fused_kernel(const float* __restrict__ imgs,
                  const float* __restrict__ gt,
                  const float* __restrict__ pr,
                  float* __restrict__ out)
{
    // ---- shared arena ----
    __shared__ __align__(16) float gsh[SZ*PX];     // g crop, x-padded
    __shared__ __align__(16) float psh[SZ*PX];     // p crop, x-padded
    __shared__ __align__(16) float tg [SZ*PY];     // hconv(g),  col-major y-padded
    __shared__ __align__(16) float tgg[SZ*PY];     // hconv(g^2)
    __shared__ __align__(16) float tp [SZ*PY];     // hconv(p)
    __shared__ __align__(16) float tpp[SZ*PY];     // hconv(p^2)
    __shared__ __align__(16) float tgp[SZ*PY];     // hconv(g*p)
    __shared__ int   gix0[SZ], gix1[SZ], giy0[SZ], giy1[SZ];
    __shared__ int   pix0[SZ], pix1[SZ], piy0[SZ], piy1[SZ];
    __shared__ float gfx[SZ], gfy[SZ], pfx[SZ], pfy[SZ];
    __shared__ int   warpsum[8], warpexc[8];
    __shared__ int   s_vlist[MAXLOCAL], s_clist[MAXLOCAL];
    __shared__ int   s_validcnt;
    __shared__ float ws[8], wl[8];
    __shared__ int   s_last;

    const int tid  = threadIdx.x;
    const int bid  = blockIdx.x;
    const int lane = tid & 31;
    const int wid  = tid >> 5;

    // zero padded tiles once (interiors overwritten per item; pads stay 0)
    for (int p = tid; p < SZ*PX; p += 256) { gsh[p] = 0.f; psh[p] = 0.f; }
    for (int p = tid; p < SZ*PY; p += 256) {
        tg[p] = 0.f; tgg[p] = 0.f; tp[p] = 0.f; tpp[p] = 0.f; tgp[p] = 0.f;
    }

    // ================= validity (redundant per block, no global sync) =======
    int flags = 0, cnt = 0;
    {
        const int base = tid * 16;
        #pragma unroll
        for (int q = 0; q < 16; q++) {
            int pair = base + q;
            int b = pair >> 10, r = pair & 1023, i = r >> 6, j = r & 63;
            const float* gb = gt + (b*NG + i)*4;
            const float* pb = pr + (b*NP + j)*4;
            float gx = gb[0], gy = gb[1], gw = gb[2], gh = gb[3];
            float px = pb[0], py = pb[1], pw = pb[2], ph = pb[3];
            float tlx = fmaxf(gx - gw*0.5f, px - pw*0.5f);
            float tly = fmaxf(gy - gh*0.5f, py - ph*0.5f);
            float brx = fminf(gx + gw*0.5f, px + pw*0.5f);
            float bry = fminf(gy + gh*0.5f, py + ph*0.5f);
            float en = ((tlx < brx) && (tly < bry)) ? 1.f : 0.f;
            float ai = (brx - tlx) * (bry - tly) * en;
            float iou = ai / (gw*gh + pw*ph - ai + 1e-16f);
            bool valid = (iou > THRESH) && (pw > 2.f) && (ph > 2.f);
            if (valid) { flags |= (1 << q); cnt++; }
        }
    }
    // warp inclusive scan
    int incl = cnt;
    #pragma unroll
    for (int d = 1; d < 32; d <<= 1) {
        int n = __shfl_up_sync(0xffffffffu, incl, d);
        if (lane >= d) incl += n;
    }
    if (lane == 31) warpsum[wid] = incl;
    __syncthreads();
    if (tid < 8) {
        int v = warpsum[tid];
        int inc2 = v;
        #pragma unroll
        for (int d = 1; d < 8; d <<= 1) {
            int n = __shfl_up_sync(0xffu, inc2, d, 8);
            if (tid >= d) inc2 += n;
        }
        warpexc[tid] = inc2 - v;
        if (tid == 7) s_validcnt = inc2;
    }
    __syncthreads();
    // record only this block's items: itp = 3*off + c with itp % GRID == bid
    {
        int off = warpexc[wid] + (incl - cnt);
        const int base = tid * 16;
        #pragma unroll
        for (int q = 0; q < 16; q++) {
            if (flags & (1 << q)) {
                #pragma unroll
                for (int c = 0; c < 3; c++) {
                    int itp = 3*off + c;
                    if (itp % GRID == bid) {
                        int m = itp / GRID;
                        if (m < MAXLOCAL) { s_vlist[m] = base + q; s_clist[m] = c; }
                    }
                }
                off++;
            }
        }
    }
    __syncthreads();

    const int vcnt   = s_validcnt;
    const int nitems = vcnt * 3;
    const int nlocal = (nitems > bid) ? ((nitems - bid + GRID - 1) / GRID) : 0;

    // ================= item loop (fully independent) ========================
    for (int m = 0; m < nlocal; m++) {
        const int pair = s_vlist[m];
        const int c    = s_clist[m];
        const int itp  = bid + m*GRID;
        const int b = pair >> 10, r = pair & 1023, i = r >> 6, j = r & 63;

        // ---- box prep: g box (tid<64), p box (64..127)
        if (tid < 128) {
            const float* box = (tid < 64) ? (gt + (b*NG + i)*4) : (pr + (b*NP + j)*4);
            int*   ox0 = (tid < 64) ? gix0 : pix0;
            int*   ox1 = (tid < 64) ? gix1 : pix1;
            int*   oy0 = (tid < 64) ? giy0 : piy0;
            int*   oy1 = (tid < 64) ? giy1 : piy1;
            float* ofx = (tid < 64) ? gfx  : pfx;
            float* ofy = (tid < 64) ? gfy  : pfy;
            const int t64 = tid & 63;
            const float cx = box[0], cy = box[1], w = box[2], h = box[3];
            if (t64 < 32) {
                float x0 = fminf(fmaxf(floorf(cx - w*0.5f), 0.f), (float)WW - 1.f);
                float x1 = fminf(fmaxf(floorf(cx + w*0.5f), 0.f), (float)WW);
                float wp = fmaxf(x1 - x0, 1.f);
                float dd = (float)t64 + 0.5f;
                float sx = x0 + fminf(fmaxf(dd*wp/(float)SZ - 0.5f, 0.f), wp - 1.f);
                float fl = floorf(sx);
                ofx[t64] = sx - fl;
                int i0   = (int)fl;
                ox0[t64] = i0;
                ox1[t64] = min(i0 + 1, (int)(x0 + wp - 1.f));
            } else {
                int t = t64 - 32;
                float y0 = fminf(fmaxf(floorf(cy - h*0.5f), 0.f), (float)HH - 1.f);
                float y1 = fminf(fmaxf(floorf(cy + h*0.5f), 0.f), (float)HH);
                float hp = fmaxf(y1 - y0, 1.f);
                float dd = (float)t + 0.5f;
                float sy = y0 + fminf(fmaxf(dd*hp/(float)SZ - 0.5f, 0.f), hp - 1.f);
                float fl = floorf(sy);
                ofy[t] = sy - fl;
                int i0 = (int)fl;
                oy0[t] = i0;
                oy1[t] = min(i0 + 1, (int)(y0 + hp - 1.f));
            }
        }
        __syncthreads();

        // ---- bilinear gathers (both boxes), thread: row=tid>>3, 4 px
        {
            const int row = tid >> 3;
            const int xq  = (tid & 7) << 2;
            const float* ic = imgs + ((size_t)b*3 + c)*HH*WW;
            {   // g
                const int j0 = giy0[row], j1 = giy1[row];
                const float fy = gfy[row];
                #pragma unroll
                for (int q = 0; q < 4; q++) {
                    int xx = xq + q;
                    int i0 = gix0[xx], i1 = gix1[xx];
                    float fx = gfx[xx];
                    gsh[row*PX + 8 + xx] =
                          ic[j0*WW + i0] * (1.f - fy) * (1.f - fx)
                        + ic[j0*WW + i1] * (1.f - fy) * fx
                        + ic[j1*WW + i0] * fy * (1.f - fx)
                        + ic[j1*WW + i1] * fy * fx;
                }
            }
            {   // p
                const int j0 = piy0[row], j1 = piy1[row];
                const float fy = pfy[row];
                #pragma unroll
                for (int q = 0; q < 4; q++) {
                    int xx = xq + q;
                    int i0 = pix0[xx], i1 = pix1[xx];
                    float fx = pfx[xx];
                    psh[row*PX + 8 + xx] =
                          ic[j0*WW + i0] * (1.f - fy) * (1.f - fx)
                        + ic[j0*WW + i1] * (1.f - fy) * fx
                        + ic[j1*WW + i0] * fy * (1.f - fx)
                        + ic[j1*WW + i1] * fy * fx;
                }
            }
        }
        __syncthreads();

        // ---- horizontal convs: g, g^2, p, p^2, g*p  (+ L1 from registers)
        float acc_l1 = 0.f;
        {
            const int row = tid >> 3;
            const int xq  = (tid & 7) << 2;
            const float* gb2 = gsh + row*PX + xq + 3;
            const float* pb2 = psh + row*PX + xq + 3;
            float gv[14], pv[14];
            #pragma unroll
            for (int k2 = 0; k2 < 14; k2++) { gv[k2] = gb2[k2]; pv[k2] = pb2[k2]; }
            #pragma unroll
            for (int q = 0; q < 4; q++)
                acc_l1 += fabsf(gv[q+5] - pv[q+5]) * (1.0f/255.0f);
            // tg
            #pragma unroll
            for (int q = 0; q < 4; q++) {
                float a = 0.f;
                #pragma unroll
                for (int t = 0; t < 11; t++) a = fmaf(GK[t], gv[q+t], a);
                tg[(xq+q)*PY + row + 5] = a;
            }
            // tgg
            #pragma unroll
            for (int q = 0; q < 4; q++) {
                float a = 0.f;
                #pragma unroll
                for (int t = 0; t < 11; t++) a = fmaf(GK[t], gv[q+t]*gv[q+t], a);
                tgg[(xq+q)*PY + row + 5] = a;
            }
            // tp
            #pragma unroll
            for (int q = 0; q < 4; q++) {
                float a = 0.f;
                #pragma unroll
                for (int t = 0; t < 11; t++) a = fmaf(GK[t], pv[q+t], a);
                tp[(xq+q)*PY + row + 5] = a;
            }
            // tpp
            #pragma unroll
            for (int q = 0; q < 4; q++) {
                float a = 0.f;
                #pragma unroll
                for (int t = 0; t < 11; t++) a = fmaf(GK[t], pv[q+t]*pv[q+t], a);
                tpp[(xq+q)*PY + row + 5] = a;
            }
            // tgp
            #pragma unroll
            for (int q = 0; q < 4; q++) {
                float a = 0.f;
                #pragma unroll
                for (int t = 0; t < 11; t++) a = fmaf(GK[t], gv[q+t]*pv[q+t], a);
                tgp[(xq+q)*PY + row + 5] = a;
            }
        }
        __syncthreads();

        // ---- vertical convs + SSIM (thread: col x, 4 rows at yq)
        float acc_ssim = 0.f;
        {
            const int x  = tid & 31;
            const int yq = (tid >> 5) << 2;
            float u[14];
            float mg[4], sg[4], mp_[4], sp[4], egp[4];
            const float* b1;
            b1 = tg + x*PY + yq;
            #pragma unroll
            for (int k2 = 0; k2 < 14; k2++) u[k2] = b1[k2];
            #pragma unroll
            for (int q = 0; q < 4; q++) {
                float a = 0.f;
                #pragma unroll
                for (int t = 0; t < 11; t++) a = fmaf(GK[t], u[q+t], a);
                mg[q] = a;
            }
            b1 = tgg + x*PY + yq;
            #pragma unroll
            for (int k2 = 0; k2 < 14; k2++) u[k2] = b1[k2];
            #pragma unroll
            for (int q = 0; q < 4; q++) {
                float a = 0.f;
                #pragma unroll
                for (int t = 0; t < 11; t++) a = fmaf(GK[t], u[q+t], a);
                sg[q] = a - mg[q]*mg[q];
            }
            b1 = tp + x*PY + yq;
            #pragma unroll
            for (int k2 = 0; k2 < 14; k2++) u[k2] = b1[k2];
            #pragma unroll
            for (int q = 0; q < 4; q++) {
                float a = 0.f;
                #pragma unroll
                for (int t = 0; t < 11; t++) a = fmaf(GK[t], u[q+t], a);
                mp_[q] = a;
            }
            b1 = tpp + x*PY + yq;
            #pragma unroll
            for (int k2 = 0; k2 < 14; k2++) u[k2] = b1[k2];
            #pragma unroll
            for (int q = 0; q < 4; q++) {
                float a = 0.f;
                #pragma unroll
                for (int t = 0; t < 11; t++) a = fmaf(GK[t], u[q+t], a);
                sp[q] = a - mp_[q]*mp_[q];
            }
            b1 = tgp + x*PY + yq;
            #pragma unroll
            for (int k2 = 0; k2 < 14; k2++) u[k2] = b1[k2];
            #pragma unroll
            for (int q = 0; q < 4; q++) {
                float a = 0.f;
                #pragma unroll
                for (int t = 0; t < 11; t++) a = fmaf(GK[t], u[q+t], a);
                egp[q] = a;
            }
            #pragma unroll
            for (int q = 0; q < 4; q++) {
                float sgp = egp[q] - mg[q]*mp_[q];
                float num = (2.f*mg[q]*mp_[q] + C1V) * (2.f*sgp + C2V);
                float den = (mg[q]*mg[q] + mp_[q]*mp_[q] + C1V) * (sg[q] + sp[q] + C2V);
                acc_ssim += num / den;
            }
        }

        // ---- block reduction and store
        #pragma unroll
        for (int o = 16; o > 0; o >>= 1) {
            acc_ssim += __shfl_down_sync(0xffffffffu, acc_ssim, o);
            acc_l1   += __shfl_down_sync(0xffffffffu, acc_l1,   o);
        }
        if (lane == 0) { ws[wid] = acc_ssim; wl[wid] = acc_l1; }
        __syncthreads();
        if (tid == 0) {
            float s = 0.f, l = 0.f;
            #pragma unroll
            for (int w = 0; w < 8; w++) { s += ws[w]; l += wl[w]; }
            d_v_ssim[itp] = s;
            d_v_l1  [itp] = l;
        }
        __syncthreads();
    }

    // ================= finalize (last block) ================================
    if (tid == 0) {
        __threadfence();
        unsigned int t = atomicAdd(&d_done, 1u);
        s_last = (t == GRID - 1u) ? 1 : 0;
    }
    __syncthreads();
    if (!s_last) return;
    __threadfence();

    float* rs = gsh;          // reuse arena
    float* rl = gsh + 256;
    float cs = 0.f, cl = 0.f;
    for (int p = tid; p < nitems; p += 256) { cs += d_v_ssim[p]; cl += d_v_l1[p]; }
    rs[tid] = cs; rl[tid] = cl;
    __syncthreads();
    #pragma unroll
    for (int s = 128; s > 0; s >>= 1) {
        if (tid < s) { rs[tid] += rs[tid+s]; rl[tid] += rl[tid+s]; }
        __syncthreads();
    }
    if (tid == 0) {
        float cntf  = (float)vcnt;
        float denom = fmaxf(cntf, 1.f) * 3.0f * (float)NPIX;
        float loss  = rl[0] / denom + 1.f - rs[0] / denom;
        out[0] = (cntf > 0.f) ? loss : 0.f;
        d_done = 0u;     // reset for next graph replay
    }
}

extern "C" void kernel_launch(void* const* d_in, const int* in_sizes, int n_in,
                              void* d_out, int out_size)
{
    const float* imgs = (const float*)d_in[0];   // (4,3,640,640)
    const float* gt   = (const float*)d_in[1];   // (4,16,4)
    const float* pr   = (const float*)d_in[2];   // (4,64,4)
    float* out = (float*)d_out;

    fused_kernel<<<GRID, 256>>>(imgs, gt, pr, out);
}

// round 7
// speedup vs baseline: 1.1044x; 1.1044x over previous
#include <cuda_runtime.h>
#include <math.h>

#define BN   4
#define NG   16
#define NP   64
#define SZ   32
#define HH   640
#define WW   640
#define NPIX 1024
#define NBOX 80
#define NPAIR 4096            // BN*NG*NP
#define C1V  6.5025f
#define C2V  58.5225f
#define THRESH 0.3f
#define PX   49               // x-padded pitch (8 left pad), odd -> conflict-free
#define PY   45               // y-padded pitch (5 top pad), odd -> conflict-free
#define NT   128              // threads per block
#define GRID 1184             // 148 SMs * 8 resident blocks (one wave)
#define CROPB (GRID-1)        // 1183 crop workers -> 1 item each
#define NBOXI (BN*NBOX*3)     // 960 crop items

// Normalized 11-tap Gaussian (sigma=1.5)
__constant__ float GK[11] = {
    0.00102838f, 0.00759870f, 0.03600077f, 0.10936100f, 0.21300570f,
    0.26601172f,
    0.21300570f, 0.10936100f, 0.03600077f, 0.00759870f, 0.00102838f
};

// Scratch (device globals; zero-initialized; reset at end of each run)
__device__ __align__(128) float d_gcrop[BN*NG*3*NPIX];
__device__ __align__(128) float d_pcrop[BN*NP*3*NPIX];
__device__ __align__(128) float d_mug  [BN*NG*3*NPIX];
__device__ __align__(128) float d_sigg [BN*NG*3*NPIX];
__device__ __align__(128) float d_mup  [BN*NP*3*NPIX];
__device__ __align__(128) float d_sigp [BN*NP*3*NPIX];
__device__ int   d_valid_cnt;
__device__ int   d_valid_idx[NPAIR];
__device__ float d_v_ssim[NPAIR*3];
__device__ float d_v_l1  [NPAIR*3];
__device__ int   d_ready[NBOXI];    // per crop-item done flags
__device__ int   d_valid_ready;
__device__ unsigned int d_done;     // finalize ticket

#define SMEMF 4640

__device__ __forceinline__ void spin_flag(const int* f) {
    while (*(volatile const int*)f == 0) __nanosleep(32);
}

__global__ __launch_bounds__(NT, 8)
void fused_kernel(const float* __restrict__ imgs,
                  const float* __restrict__ gt,
                  const float* __restrict__ pr,
                  float* __restrict__ out)
{
    __shared__ __align__(16) float S[SMEMF];
    __shared__ int s_last;
    const int tid  = threadIdx.x;
    const int bid  = blockIdx.x;
    const int lane = tid & 31;
    const int wid  = tid >> 5;

    float* csh = S;                 // [SZ*PX]  crop tile / pair product tile
    float* t1  = S + 1568;          // [SZ*PY]
    float* t2  = S + 3008;          // [SZ*PY]  (phase-1 only)
    int*   ix0s = (int*)(S + 4448);
    int*   ix1s = (int*)(S + 4480);
    int*   iy0s = (int*)(S + 4512);
    int*   iy1s = (int*)(S + 4544);
    float* fxs  = S + 4576;
    float* fys  = S + 4608;
    float* ws   = S + 4448;         // [4] (phase-2 reuse of idx area)
    float* wl   = S + 4456;         // [4]

    // zero arena once (pads stay zero; interiors overwritten per item)
    for (int p = tid; p < 4448; p += NT) S[p] = 0.f;
    __syncthreads();

    // ================= PHASE 1 =============================================
    if (bid == 0) {
        // ---- validity + compaction (runs immediately; 32 pairs/thread)
        __shared__ int warpsum[4];
        int flags = 0, cnt = 0;
        const int base = tid * 32;
        #pragma unroll
        for (int q = 0; q < 32; q++) {
            int pair = base + q;
            int b = pair >> 10, r = pair & 1023, i = r >> 6, j = r & 63;
            const float* gb = gt + (b*NG + i)*4;
            const float* pb = pr + (b*NP + j)*4;
            float gx = gb[0], gy = gb[1], gw = gb[2], gh = gb[3];
            float px = pb[0], py = pb[1], pw = pb[2], ph = pb[3];
            float tlx = fmaxf(gx - gw*0.5f, px - pw*0.5f);
            float tly = fmaxf(gy - gh*0.5f, py - ph*0.5f);
            float brx = fminf(gx + gw*0.5f, px + pw*0.5f);
            float bry = fminf(gy + gh*0.5f, py + ph*0.5f);
            float en = ((tlx < brx) && (tly < bry)) ? 1.f : 0.f;
            float ai = (brx - tlx) * (bry - tly) * en;
            float iou = ai / (gw*gh + pw*ph - ai + 1e-16f);
            bool valid = (iou > THRESH) && (pw > 2.f) && (ph > 2.f);
            if (valid) { flags |= (1 << q); cnt++; }
        }
        // warp inclusive scan of counts
        int incl = cnt;
        #pragma unroll
        for (int d = 1; d < 32; d <<= 1) {
            int n = __shfl_up_sync(0xffffffffu, incl, d);
            if (lane >= d) incl += n;
        }
        if (lane == 31) warpsum[wid] = incl;
        __syncthreads();
        int wexc = 0;
        #pragma unroll
        for (int w = 0; w < 4; w++) if (w < wid) wexc += warpsum[w];
        int off = wexc + (incl - cnt);
        #pragma unroll
        for (int q = 0; q < 32; q++)
            if (flags & (1 << q)) d_valid_idx[off++] = base + q;
        if (tid == NT-1) d_valid_cnt = wexc + incl;   // total
        __threadfence();
        __syncthreads();
        if (tid == 0) d_valid_ready = 1;
        __syncthreads();
    } else if (bid - 1 < NBOXI) {
        const int it  = bid - 1;              // exactly one crop item
        const int b   = it / (NBOX*3);
        const int rem = it % (NBOX*3);
        const int k   = rem / 3;
        const int c   = rem % 3;
        const bool isGT = (k < NG);
        const int  bi   = isGT ? (b*NG + k) : (b*NP + (k - NG));

        const float* box = isGT ? (gt + (b*NG + k)*4) : (pr + (b*NP + (k-NG))*4);
        float* crop_out  = (isGT ? d_gcrop : d_pcrop) + (size_t)bi*3*NPIX + c*NPIX;
        float* mu_out    = (isGT ? d_mug   : d_mup  ) + (size_t)bi*3*NPIX + c*NPIX;
        float* sig_out   = (isGT ? d_sigg  : d_sigp ) + (size_t)bi*3*NPIX + c*NPIX;

        if (tid < 64) {
            const float cx = box[0], cy = box[1], w = box[2], h = box[3];
            if (tid < 32) {
                float x0 = fminf(fmaxf(floorf(cx - w*0.5f), 0.f), (float)WW - 1.f);
                float x1 = fminf(fmaxf(floorf(cx + w*0.5f), 0.f), (float)WW);
                float wp = fmaxf(x1 - x0, 1.f);
                float dd = (float)tid + 0.5f;
                float sx = x0 + fminf(fmaxf(dd*wp/(float)SZ - 0.5f, 0.f), wp - 1.f);
                float fl = floorf(sx);
                fxs[tid]  = sx - fl;
                int i0    = (int)fl;
                ix0s[tid] = i0;
                ix1s[tid] = min(i0 + 1, (int)(x0 + wp - 1.f));
            } else {
                int t = tid - 32;
                float y0 = fminf(fmaxf(floorf(cy - h*0.5f), 0.f), (float)HH - 1.f);
                float y1 = fminf(fmaxf(floorf(cy + h*0.5f), 0.f), (float)HH);
                float hp = fmaxf(y1 - y0, 1.f);
                float dd = (float)t + 0.5f;
                float sy = y0 + fminf(fmaxf(dd*hp/(float)SZ - 0.5f, 0.f), hp - 1.f);
                float fl = floorf(sy);
                fys[t]  = sy - fl;
                int i0  = (int)fl;
                iy0s[t] = i0;
                iy1s[t] = min(i0 + 1, (int)(y0 + hp - 1.f));
            }
        }
        __syncthreads();

        // bilinear gather: 8 px/thread via 2 reps of the 4-px pattern
        {
            const float* ic = imgs + ((size_t)b*3 + c)*HH*WW;
            #pragma unroll
            for (int rep = 0; rep < 2; rep++) {
                const int idx = tid + rep*NT;
                const int row = idx >> 3;
                const int xq  = (idx & 7) << 2;
                const int j0 = iy0s[row], j1 = iy1s[row];
                const float fy = fys[row];
                float4 vout;
                float* vp = (float*)&vout;
                #pragma unroll
                for (int q = 0; q < 4; q++) {
                    int xx = xq + q;
                    int i0 = ix0s[xx], i1 = ix1s[xx];
                    float fx = fxs[xx];
                    float v = ic[j0*WW + i0] * (1.f - fy) * (1.f - fx)
                            + ic[j0*WW + i1] * (1.f - fy) * fx
                            + ic[j1*WW + i0] * fy * (1.f - fx)
                            + ic[j1*WW + i1] * fy * fx;
                    csh[row*PX + 8 + xx] = v;
                    vp[q] = v;
                }
                *(float4*)(crop_out + row*SZ + xq) = vout;
            }
        }
        __syncthreads();

        // horizontal conv of x and x^2
        #pragma unroll
        for (int rep = 0; rep < 2; rep++) {
            const int idx = tid + rep*NT;
            const int row = idx >> 3;
            const int xq  = (idx & 7) << 2;
            const float* base = csh + row*PX + xq + 3;
            float in[14], sq[14];
            #pragma unroll
            for (int k2 = 0; k2 < 14; k2++) { in[k2] = base[k2]; sq[k2] = in[k2]*in[k2]; }
            #pragma unroll
            for (int q = 0; q < 4; q++) {
                float a = 0.f, bb = 0.f;
                #pragma unroll
                for (int t = 0; t < 11; t++) {
                    a  = fmaf(GK[t], in[q+t], a);
                    bb = fmaf(GK[t], sq[q+t], bb);
                }
                t1[(xq+q)*PY + row + 5] = a;
                t2[(xq+q)*PY + row + 5] = bb;
            }
        }
        __syncthreads();

        // vertical conv -> mu, sigma
        #pragma unroll
        for (int rep = 0; rep < 2; rep++) {
            const int idx = tid + rep*NT;
            const int x   = idx & 31;
            const int yq  = (idx >> 5) << 2;
            const float* b1 = t1 + x*PY + yq;
            const float* b2 = t2 + x*PY + yq;
            float u1[14], u2[14];
            #pragma unroll
            for (int k2 = 0; k2 < 14; k2++) { u1[k2] = b1[k2]; u2[k2] = b2[k2]; }
            #pragma unroll
            for (int q = 0; q < 4; q++) {
                float a = 0.f, bb = 0.f;
                #pragma unroll
                for (int t = 0; t < 11; t++) {
                    a  = fmaf(GK[t], u1[q+t], a);
                    bb = fmaf(GK[t], u2[q+t], bb);
                }
                mu_out [(yq+q)*SZ + x] = a;
                sig_out[(yq+q)*SZ + x] = bb - a*a;
            }
        }
        __threadfence();
        __syncthreads();
        if (tid == 0) d_ready[it] = 1;
        __syncthreads();
    }

    // ================= PHASE 2: pairs, gated by per-item flags ==============
    if (tid == 0) { spin_flag(&d_valid_ready); __threadfence(); }
    __syncthreads();
    const int nitems = d_valid_cnt * 3;

    for (int itp = bid; itp < nitems; itp += GRID) {
        const int v = itp / 3;
        const int c = itp - v*3;
        const int pair = d_valid_idx[v];
        const int b = pair >> 10, r = pair & 1023, i = r >> 6, j = r & 63;

        if (tid == 0) {
            spin_flag(&d_ready[b*(NBOX*3) + i*3 + c]);
            spin_flag(&d_ready[b*(NBOX*3) + (NG + j)*3 + c]);
            __threadfence();
        }
        __syncthreads();

        const float* gbase = d_gcrop + ((size_t)(b*NG + i)*3 + c)*NPIX;
        const float* pbase = d_pcrop + ((size_t)(b*NP + j)*3 + c)*NPIX;
        const float* mug   = d_mug   + ((size_t)(b*NG + i)*3 + c)*NPIX;
        const float* sigg  = d_sigg  + ((size_t)(b*NG + i)*3 + c)*NPIX;
        const float* mup   = d_mup   + ((size_t)(b*NP + j)*3 + c)*NPIX;
        const float* sigp  = d_sigp  + ((size_t)(b*NP + j)*3 + c)*NPIX;

        float acc_ssim = 0.f, acc_l1 = 0.f;

        // load g,p; product -> smem; L1 in registers
        #pragma unroll
        for (int rep = 0; rep < 2; rep++) {
            const int idx = tid + rep*NT;
            const int row = idx >> 3;
            const int xq  = (idx & 7) << 2;
            float4 g4 = *(const float4*)(gbase + row*SZ + xq);
            float4 p4 = *(const float4*)(pbase + row*SZ + xq);
            const float* gp = (const float*)&g4;
            const float* pp = (const float*)&p4;
            #pragma unroll
            for (int q = 0; q < 4; q++) {
                csh[row*PX + 8 + xq + q] = gp[q] * pp[q];
                acc_l1 += fabsf(gp[q] - pp[q]) * (1.0f/255.0f);
            }
        }
        __syncthreads();

        // horizontal conv of product
        #pragma unroll
        for (int rep = 0; rep < 2; rep++) {
            const int idx = tid + rep*NT;
            const int row = idx >> 3;
            const int xq  = (idx & 7) << 2;
            const float* base = csh + row*PX + xq + 3;
            float in[14];
            #pragma unroll
            for (int k2 = 0; k2 < 14; k2++) in[k2] = base[k2];
            #pragma unroll
            for (int q = 0; q < 4; q++) {
                float a = 0.f;
                #pragma unroll
                for (int t = 0; t < 11; t++) a = fmaf(GK[t], in[q+t], a);
                t1[(xq+q)*PY + row + 5] = a;
            }
        }
        __syncthreads();

        // vertical conv + SSIM
        #pragma unroll
        for (int rep = 0; rep < 2; rep++) {
            const int idx = tid + rep*NT;
            const int x   = idx & 31;
            const int yq  = (idx >> 5) << 2;
            const float* b1 = t1 + x*PY + yq;
            float u[14];
            #pragma unroll
            for (int k2 = 0; k2 < 14; k2++) u[k2] = b1[k2];
            #pragma unroll
            for (int q = 0; q < 4; q++) {
                float egp = 0.f;
                #pragma unroll
                for (int t = 0; t < 11; t++) egp = fmaf(GK[t], u[q+t], egp);
                const int p = (yq+q)*SZ + x;
                float mg  = mug [p];
                float mp_ = mup [p];
                float sg  = sigg[p];
                float sp  = sigp[p];
                float sgp = egp - mg*mp_;
                float num = (2.f*mg*mp_ + C1V) * (2.f*sgp + C2V);
                float den = (mg*mg + mp_*mp_ + C1V) * (sg + sp + C2V);
                acc_ssim += num / den;
            }
        }

        #pragma unroll
        for (int o = 16; o > 0; o >>= 1) {
            acc_ssim += __shfl_down_sync(0xffffffffu, acc_ssim, o);
            acc_l1   += __shfl_down_sync(0xffffffffu, acc_l1,   o);
        }
        if (lane == 0) { ws[wid] = acc_ssim; wl[wid] = acc_l1; }
        __syncthreads();
        if (tid == 0) {
            float s = 0.f, l = 0.f;
            #pragma unroll
            for (int w = 0; w < 4; w++) { s += ws[w]; l += wl[w]; }
            d_v_ssim[itp] = s;
            d_v_l1  [itp] = l;
        }
        __syncthreads();
    }

    // ================= PHASE 3: fused finalize (last block) =================
    if (tid == 0) {
        __threadfence();
        unsigned int t = atomicAdd(&d_done, 1u);
        s_last = (t == GRID - 1u) ? 1 : 0;
    }
    __syncthreads();
    if (!s_last) return;
    __threadfence();

    float* rs = S;
    float* rl = S + NT;
    float cs = 0.f, cl = 0.f;
    for (int p = tid; p < nitems; p += NT) { cs += d_v_ssim[p]; cl += d_v_l1[p]; }
    rs[tid] = cs; rl[tid] = cl;
    __syncthreads();
    #pragma unroll
    for (int s = NT/2; s > 0; s >>= 1) {
        if (tid < s) { rs[tid] += rs[tid+s]; rl[tid] += rl[tid+s]; }
        __syncthreads();
    }
    // reset flags for next graph replay
    for (int p = tid; p < NBOXI; p += NT) d_ready[p] = 0;
    if (tid == 0) {
        float cnt   = (float)d_valid_cnt;
        float denom = fmaxf(cnt, 1.f) * 3.0f * (float)NPIX;
        float loss  = rl[0] / denom + 1.f - rs[0] / denom;
        out[0] = (cnt > 0.f) ? loss : 0.f;
        d_valid_ready = 0;
        d_done        = 0u;
    }
}

extern "C" void kernel_launch(void* const* d_in, const int* in_sizes, int n_in,
                              void* d_out, int out_size)
{
    const float* imgs = (const float*)d_in[0];   // (4,3,640,640)
    const float* gt   = (const float*)d_in[1];   // (4,16,4)
    const float* pr   = (const float*)d_in[2];   // (4,64,4)
    float* out = (float*)d_out;

    fused_kernel<<<GRID, NT>>>(imgs, gt, pr, out);
}

// round 8
// speedup vs baseline: 1.2971x; 1.1745x over previous
#include <cuda_runtime.h>
#include <math.h>

#define BN   4
#define NG   16
#define NP   64
#define SZ   32
#define HH   640
#define WW   640
#define NPIX 1024
#define NBOX 80
#define NPAIR 4096            // BN*NG*NP
#define C1V  6.5025f
#define C2V  58.5225f
#define THRESH 0.3f
#define PY   45               // y-padded col-major pitch (5 top pad), odd -> conflict-free
#define NT   256
#define OCCB 5                // blocks per SM
#define GRID (148*OCCB)       // 740
#define CROPB (GRID-1)        // 739 crop workers
#define NBOXI (BN*NBOX*3)     // 960 crop items

// Normalized 11-tap Gaussian (sigma=1.5)
__constant__ float GK[11] = {
    0.00102838f, 0.00759870f, 0.03600077f, 0.10936100f, 0.21300570f,
    0.26601172f,
    0.21300570f, 0.10936100f, 0.03600077f, 0.00759870f, 0.00102838f
};

// Scratch (device globals; zero-initialized; counters reset at end of each run)
__device__ __align__(128) float d_gcrop[BN*NG*3*NPIX];
__device__ __align__(128) float d_pcrop[BN*NP*3*NPIX];
__device__ __align__(128) float d_mug  [BN*NG*3*NPIX];
__device__ __align__(128) float d_sigg [BN*NG*3*NPIX];
__device__ __align__(128) float d_mup  [BN*NP*3*NPIX];
__device__ __align__(128) float d_sigp [BN*NP*3*NPIX];
__device__ int   d_valid_cnt;
__device__ int   d_valid_idx[NPAIR];
__device__ float d_v_ssim[NPAIR*3];
__device__ float d_v_l1  [NPAIR*3];
__device__ int   d_ready[NBOXI];
__device__ int   d_valid_ready;
__device__ unsigned int d_done;

__device__ __forceinline__ void spin_flag(const int* f) {
    while (*(volatile const int*)f == 0) __nanosleep(32);
}

// shuffle with zero outside [0,32)
__device__ __forceinline__ float shz(float v, int src) {
    float s = __shfl_sync(0xffffffffu, v, src & 31);
    return ((unsigned)src < 32u) ? s : 0.f;
}

__global__ __launch_bounds__(NT, OCCB)
void fused_kernel(const float* __restrict__ imgs,
                  const float* __restrict__ gt,
                  const float* __restrict__ pr,
                  float* __restrict__ out)
{
    __shared__ __align__(16) float t1[SZ*PY];   // col-major, y-padded
    __shared__ __align__(16) float t2[SZ*PY];   // (crop items only)
    __shared__ float ws[8], wl[8];
    __shared__ int   warpsum[8];
    __shared__ int   s_last;

    const int tid  = threadIdx.x;
    const int bid  = blockIdx.x;
    const int lane = tid & 31;
    const int wid  = tid >> 5;

    // zero pads once (interiors fully overwritten per item)
    for (int p = tid; p < SZ*PY; p += NT) { t1[p] = 0.f; t2[p] = 0.f; }
    __syncthreads();

    // ================= PHASE 1 =============================================
    if (bid == 0) {
        // validity + compaction: 16 pairs/thread, warp-scan compaction
        int flags = 0, cnt = 0;
        const int base = tid * 16;
        #pragma unroll
        for (int q = 0; q < 16; q++) {
            int pair = base + q;
            int b = pair >> 10, r = pair & 1023, i = r >> 6, j = r & 63;
            const float* gb = gt + (b*NG + i)*4;
            const float* pb = pr + (b*NP + j)*4;
            float gx = gb[0], gy = gb[1], gw = gb[2], gh = gb[3];
            float px = pb[0], py = pb[1], pw = pb[2], ph = pb[3];
            float tlx = fmaxf(gx - gw*0.5f, px - pw*0.5f);
            float tly = fmaxf(gy - gh*0.5f, py - ph*0.5f);
            float brx = fminf(gx + gw*0.5f, px + pw*0.5f);
            float bry = fminf(gy + gh*0.5f, py + ph*0.5f);
            float en = ((tlx < brx) && (tly < bry)) ? 1.f : 0.f;
            float ai = (brx - tlx) * (bry - tly) * en;
            float iou = ai / (gw*gh + pw*ph - ai + 1e-16f);
            bool valid = (iou > THRESH) && (pw > 2.f) && (ph > 2.f);
            if (valid) { flags |= (1 << q); cnt++; }
        }
        int incl = cnt;
        #pragma unroll
        for (int d = 1; d < 32; d <<= 1) {
            int n = __shfl_up_sync(0xffffffffu, incl, d);
            if (lane >= d) incl += n;
        }
        if (lane == 31) warpsum[wid] = incl;
        __syncthreads();
        int wexc = 0;
        #pragma unroll
        for (int w = 0; w < 8; w++) if (w < wid) wexc += warpsum[w];
        int off = wexc + (incl - cnt);
        #pragma unroll
        for (int q = 0; q < 16; q++)
            if (flags & (1 << q)) d_valid_idx[off++] = base + q;
        if (tid == NT-1) d_valid_cnt = wexc + incl;
        __threadfence();
        __syncthreads();
        if (tid == 0) d_valid_ready = 1;
    } else {
        for (int it = bid - 1; it < NBOXI; it += CROPB) {
            const int b   = it / (NBOX*3);
            const int rem = it % (NBOX*3);
            const int k   = rem / 3;
            const int c   = rem % 3;
            const bool isGT = (k < NG);
            const int  bi   = isGT ? (b*NG + k) : (b*NP + (k - NG));

            const float* box = isGT ? (gt + (b*NG + k)*4) : (pr + (b*NP + (k-NG))*4);
            float* crop_out  = (isGT ? d_gcrop : d_pcrop) + (size_t)bi*3*NPIX + c*NPIX;
            float* mu_out    = (isGT ? d_mug   : d_mup  ) + (size_t)bi*3*NPIX + c*NPIX;
            float* sig_out   = (isGT ? d_sigg  : d_sigp ) + (size_t)bi*3*NPIX + c*NPIX;

            // per-thread coords (no smem, no sync): column = lane, rows = wid*4+q
            const float cx = box[0], cy = box[1], w = box[2], h = box[3];
            int ix0, ix1; float fx;
            {
                float x0 = fminf(fmaxf(floorf(cx - w*0.5f), 0.f), (float)WW - 1.f);
                float x1 = fminf(fmaxf(floorf(cx + w*0.5f), 0.f), (float)WW);
                float wp = fmaxf(x1 - x0, 1.f);
                float dd = (float)lane + 0.5f;
                float sx = x0 + fminf(fmaxf(dd*wp/(float)SZ - 0.5f, 0.f), wp - 1.f);
                float fl = floorf(sx);
                fx = sx - fl;
                ix0 = (int)fl;
                ix1 = min(ix0 + 1, (int)(x0 + wp - 1.f));
            }
            int iy0[4], iy1[4]; float fy[4];
            {
                float y0 = fminf(fmaxf(floorf(cy - h*0.5f), 0.f), (float)HH - 1.f);
                float y1 = fminf(fmaxf(floorf(cy + h*0.5f), 0.f), (float)HH);
                float hp = fmaxf(y1 - y0, 1.f);
                int ylim = (int)(y0 + hp - 1.f);
                #pragma unroll
                for (int q = 0; q < 4; q++) {
                    float dd = (float)(wid*4 + q) + 0.5f;
                    float sy = y0 + fminf(fmaxf(dd*hp/(float)SZ - 0.5f, 0.f), hp - 1.f);
                    float fl = floorf(sy);
                    fy[q]  = sy - fl;
                    iy0[q] = (int)fl;
                    iy1[q] = min(iy0[q] + 1, ylim);
                }
            }

            // gather (registers) + crop store
            const float* ic = imgs + ((size_t)b*3 + c)*HH*WW;
            float v[4];
            #pragma unroll
            for (int q = 0; q < 4; q++) {
                float a00 = ic[iy0[q]*WW + ix0];
                float a01 = ic[iy0[q]*WW + ix1];
                float a10 = ic[iy1[q]*WW + ix0];
                float a11 = ic[iy1[q]*WW + ix1];
                float f = fy[q];
                v[q] = a00*(1.f-f)*(1.f-fx) + a01*(1.f-f)*fx
                     + a10*f*(1.f-fx)       + a11*f*fx;
                crop_out[(wid*4+q)*SZ + lane] = v[q];
            }

            // horizontal conv via shuffles -> col-major smem
            #pragma unroll
            for (int q = 0; q < 4; q++) {
                float a = 0.f, bb = 0.f;
                #pragma unroll
                for (int t = 0; t < 11; t++) {
                    float sh = shz(v[q], lane - 5 + t);
                    a  = fmaf(GK[t], sh,    a);
                    bb = fmaf(GK[t], sh*sh, bb);
                }
                t1[lane*PY + (wid*4+q) + 5] = a;
                t2[lane*PY + (wid*4+q) + 5] = bb;
            }
            __syncthreads();

            // vertical conv: column x = tid&31, 4 rows at yq
            {
                const int x  = tid & 31;
                const int yq = (tid >> 5) << 2;
                const float* b1 = t1 + x*PY + yq;
                const float* b2 = t2 + x*PY + yq;
                float u1[14], u2[14];
                #pragma unroll
                for (int k2 = 0; k2 < 14; k2++) { u1[k2] = b1[k2]; u2[k2] = b2[k2]; }
                #pragma unroll
                for (int q = 0; q < 4; q++) {
                    float a = 0.f, bb = 0.f;
                    #pragma unroll
                    for (int t = 0; t < 11; t++) {
                        a  = fmaf(GK[t], u1[q+t], a);
                        bb = fmaf(GK[t], u2[q+t], bb);
                    }
                    mu_out [(yq+q)*SZ + x] = a;
                    sig_out[(yq+q)*SZ + x] = bb - a*a;
                }
            }
            __threadfence();
            __syncthreads();
            if (tid == 0) d_ready[it] = 1;
            __syncthreads();   // flag ordered before smem reuse
        }
    }

    // ================= PHASE 2: pairs ======================================
    if (tid == 0) { spin_flag(&d_valid_ready); __threadfence(); }
    __syncthreads();
    const int nitems = d_valid_cnt * 3;

    for (int itp = bid; itp < nitems; itp += GRID) {
        const int v = itp / 3;
        const int c = itp - v*3;
        const int pair = d_valid_idx[v];
        const int b = pair >> 10, r = pair & 1023, i = r >> 6, j = r & 63;

        if (tid == 0) {
            spin_flag(&d_ready[b*(NBOX*3) + i*3 + c]);
            spin_flag(&d_ready[b*(NBOX*3) + (NG + j)*3 + c]);
            __threadfence();
        }
        __syncthreads();

        const float* gbase = d_gcrop + ((size_t)(b*NG + i)*3 + c)*NPIX;
        const float* pbase = d_pcrop + ((size_t)(b*NP + j)*3 + c)*NPIX;
        const float* mug   = d_mug   + ((size_t)(b*NG + i)*3 + c)*NPIX;
        const float* sigg  = d_sigg  + ((size_t)(b*NG + i)*3 + c)*NPIX;
        const float* mup   = d_mup   + ((size_t)(b*NP + j)*3 + c)*NPIX;
        const float* sigp  = d_sigp  + ((size_t)(b*NP + j)*3 + c)*NPIX;

        float acc_ssim = 0.f, acc_l1 = 0.f;

        // load g,p rows (coalesced), product in registers, L1 accumulate
        float gp[4];
        #pragma unroll
        for (int q = 0; q < 4; q++) {
            const int p = (wid*4+q)*SZ + lane;
            float gv = gbase[p];
            float pv = pbase[p];
            gp[q] = gv * pv;
            acc_l1 += fabsf(gv - pv) * (1.0f/255.0f);
        }

        // horizontal conv of product via shuffles
        #pragma unroll
        for (int q = 0; q < 4; q++) {
            float a = 0.f;
            #pragma unroll
            for (int t = 0; t < 11; t++)
                a = fmaf(GK[t], shz(gp[q], lane - 5 + t), a);
            t1[lane*PY + (wid*4+q) + 5] = a;
        }
        __syncthreads();

        // vertical conv + SSIM
        {
            const int x  = tid & 31;
            const int yq = (tid >> 5) << 2;
            const float* b1 = t1 + x*PY + yq;
            float u[14];
            #pragma unroll
            for (int k2 = 0; k2 < 14; k2++) u[k2] = b1[k2];
            #pragma unroll
            for (int q = 0; q < 4; q++) {
                float egp = 0.f;
                #pragma unroll
                for (int t = 0; t < 11; t++) egp = fmaf(GK[t], u[q+t], egp);
                const int p = (yq+q)*SZ + x;
                float mg  = mug [p];
                float mp_ = mup [p];
                float sg  = sigg[p];
                float sp  = sigp[p];
                float sgp = egp - mg*mp_;
                float num = (2.f*mg*mp_ + C1V) * (2.f*sgp + C2V);
                float den = (mg*mg + mp_*mp_ + C1V) * (sg + sp + C2V);
                acc_ssim += num / den;
            }
        }

        #pragma unroll
        for (int o = 16; o > 0; o >>= 1) {
            acc_ssim += __shfl_down_sync(0xffffffffu, acc_ssim, o);
            acc_l1   += __shfl_down_sync(0xffffffffu, acc_l1,   o);
        }
        if (lane == 0) { ws[wid] = acc_ssim; wl[wid] = acc_l1; }
        __syncthreads();
        if (tid == 0) {
            float s = 0.f, l = 0.f;
            #pragma unroll
            for (int w = 0; w < 8; w++) { s += ws[w]; l += wl[w]; }
            d_v_ssim[itp] = s;
            d_v_l1  [itp] = l;
        }
        __syncthreads();
    }

    // ================= PHASE 3: fused finalize ==============================
    if (tid == 0) {
        __threadfence();
        unsigned int t = atomicAdd(&d_done, 1u);
        s_last = (t == GRID - 1u) ? 1 : 0;
    }
    __syncthreads();
    if (!s_last) return;
    __threadfence();

    float* rs = t1;            // reuse smem
    float* rl = t1 + NT;
    float cs = 0.f, cl = 0.f;
    for (int p = tid; p < nitems; p += NT) { cs += d_v_ssim[p]; cl += d_v_l1[p]; }
    rs[tid] = cs; rl[tid] = cl;
    __syncthreads();
    #pragma unroll
    for (int s = NT/2; s > 0; s >>= 1) {
        if (tid < s) { rs[tid] += rs[tid+s]; rl[tid] += rl[tid+s]; }
        __syncthreads();
    }
    for (int p = tid; p < NBOXI; p += NT) d_ready[p] = 0;   // reset for replay
    if (tid == 0) {
        float cnt   = (float)d_valid_cnt;
        float denom = fmaxf(cnt, 1.f) * 3.0f * (float)NPIX;
        float loss  = rl[0] / denom + 1.f - rs[0] / denom;
        out[0] = (cnt > 0.f) ? loss : 0.f;
        d_valid_ready = 0;
        d_done        = 0u;
    }
}

extern "C" void kernel_launch(void* const* d_in, const int* in_sizes, int n_in,
                              void* d_out, int out_size)
{
    const float* imgs = (const float*)d_in[0];   // (4,3,640,640)
    const float* gt   = (const float*)d_in[1];   // (4,16,4)
    const float* pr   = (const float*)d_in[2];   // (4,64,4)
    float* out = (float*)d_out;

    fused_kernel<<<GRID, NT>>>(imgs, gt, pr, out);
}

// round 9
// speedup vs baseline: 1.4093x; 1.0865x over previous
#include <cuda_runtime.h>
#include <math.h>

#define BN   4
#define NG   16
#define NP   64
#define SZ   32
#define HH   640
#define WW   640
#define NPIX 1024
#define NBOX 80
#define NPAIR 4096            // BN*NG*NP
#define C1V  6.5025f
#define C2V  58.5225f
#define THRESH 0.3f
#define PY   45               // y-padded col-major pitch (5 top pad), odd -> conflict-free
#define NT   256
#define OCCB 6                // blocks per SM
#define GRID (148*OCCB)       // 888
#define CROPB (GRID-1)        // 887 crop workers
#define NBOXI (BN*NBOX*3)     // 960 crop items

// Normalized 11-tap Gaussian (sigma=1.5)
__constant__ float GK[11] = {
    0.00102838f, 0.00759870f, 0.03600077f, 0.10936100f, 0.21300570f,
    0.26601172f,
    0.21300570f, 0.10936100f, 0.03600077f, 0.00759870f, 0.00102838f
};

// Scratch (device globals; zero-initialized; counters reset at end of each run)
__device__ __align__(128) float d_gcrop[BN*NG*3*NPIX];
__device__ __align__(128) float d_pcrop[BN*NP*3*NPIX];
__device__ __align__(128) float d_mug  [BN*NG*3*NPIX];
__device__ __align__(128) float d_sigg [BN*NG*3*NPIX];
__device__ __align__(128) float d_mup  [BN*NP*3*NPIX];
__device__ __align__(128) float d_sigp [BN*NP*3*NPIX];
__device__ int   d_valid_cnt;
__device__ int   d_valid_idx[NPAIR];
__device__ float d_v_ssim[NPAIR*3];
__device__ float d_v_l1  [NPAIR*3];
__device__ int   d_ready[NBOXI];
__device__ int   d_valid_ready;
__device__ unsigned int d_done;

__device__ __forceinline__ void spin_flag(const int* f) {
    while (*(volatile const int*)f == 0) __nanosleep(32);
}

__global__ __launch_bounds__(NT, OCCB)
void fused_kernel(const float* __restrict__ imgs,
                  const float* __restrict__ gt,
                  const float* __restrict__ pr,
                  float* __restrict__ out)
{
    __shared__ __align__(16) float t1[SZ*PY];   // col-major, y-padded
    __shared__ __align__(16) float t2[SZ*PY];   // (crop items only)
    __shared__ float ws[8], wl[8];
    __shared__ int   warpsum[8];
    __shared__ int   s_last;

    const int tid  = threadIdx.x;
    const int bid  = blockIdx.x;
    const int lane = tid & 31;
    const int wid  = tid >> 5;

    // zero pads once (interiors fully overwritten per item)
    for (int p = tid; p < SZ*PY; p += NT) { t1[p] = 0.f; t2[p] = 0.f; }
    __syncthreads();

    // ================= PHASE 1 =============================================
    if (bid == 0) {
        // validity + compaction: 16 pairs/thread, warp-scan compaction
        int flags = 0, cnt = 0;
        const int base = tid * 16;
        #pragma unroll
        for (int q = 0; q < 16; q++) {
            int pair = base + q;
            int b = pair >> 10, r = pair & 1023, i = r >> 6, j = r & 63;
            const float* gb = gt + (b*NG + i)*4;
            const float* pb = pr + (b*NP + j)*4;
            float gx = gb[0], gy = gb[1], gw = gb[2], gh = gb[3];
            float px = pb[0], py = pb[1], pw = pb[2], ph = pb[3];
            float tlx = fmaxf(gx - gw*0.5f, px - pw*0.5f);
            float tly = fmaxf(gy - gh*0.5f, py - ph*0.5f);
            float brx = fminf(gx + gw*0.5f, px + pw*0.5f);
            float bry = fminf(gy + gh*0.5f, py + ph*0.5f);
            float en = ((tlx < brx) && (tly < bry)) ? 1.f : 0.f;
            float ai = (brx - tlx) * (bry - tly) * en;
            float iou = ai / (gw*gh + pw*ph - ai + 1e-16f);
            bool valid = (iou > THRESH) && (pw > 2.f) && (ph > 2.f);
            if (valid) { flags |= (1 << q); cnt++; }
        }
        int incl = cnt;
        #pragma unroll
        for (int d = 1; d < 32; d <<= 1) {
            int n = __shfl_up_sync(0xffffffffu, incl, d);
            if (lane >= d) incl += n;
        }
        if (lane == 31) warpsum[wid] = incl;
        __syncthreads();
        int wexc = 0;
        #pragma unroll
        for (int w = 0; w < 8; w++) if (w < wid) wexc += warpsum[w];
        int off = wexc + (incl - cnt);
        #pragma unroll
        for (int q = 0; q < 16; q++)
            if (flags & (1 << q)) d_valid_idx[off++] = base + q;
        if (tid == NT-1) d_valid_cnt = wexc + incl;
        __threadfence();
        __syncthreads();
        if (tid == 0) d_valid_ready = 1;
    } else {
        for (int it = bid - 1; it < NBOXI; it += CROPB) {
            const int b   = it / (NBOX*3);
            const int rem = it % (NBOX*3);
            const int k   = rem / 3;
            const int c   = rem % 3;
            const bool isGT = (k < NG);
            const int  bi   = isGT ? (b*NG + k) : (b*NP + (k - NG));

            const float* box = isGT ? (gt + (b*NG + k)*4) : (pr + (b*NP + (k-NG))*4);
            float* crop_out  = (isGT ? d_gcrop : d_pcrop) + (size_t)bi*3*NPIX + c*NPIX;
            float* mu_out    = (isGT ? d_mug   : d_mup  ) + (size_t)bi*3*NPIX + c*NPIX;
            float* sig_out   = (isGT ? d_sigg  : d_sigp ) + (size_t)bi*3*NPIX + c*NPIX;

            // per-thread coords: column = lane, rows = wid*4+q
            const float cx = box[0], cy = box[1], w = box[2], h = box[3];
            int ix0, ix1; float fx;
            {
                float x0 = fminf(fmaxf(floorf(cx - w*0.5f), 0.f), (float)WW - 1.f);
                float x1 = fminf(fmaxf(floorf(cx + w*0.5f), 0.f), (float)WW);
                float wp = fmaxf(x1 - x0, 1.f);
                float dd = (float)lane + 0.5f;
                float sx = x0 + fminf(fmaxf(dd*wp/(float)SZ - 0.5f, 0.f), wp - 1.f);
                float fl = floorf(sx);
                fx = sx - fl;
                ix0 = (int)fl;
                ix1 = min(ix0 + 1, (int)(x0 + wp - 1.f));
            }
            float v[4];
            {
                float y0 = fminf(fmaxf(floorf(cy - h*0.5f), 0.f), (float)HH - 1.f);
                float y1 = fminf(fmaxf(floorf(cy + h*0.5f), 0.f), (float)HH);
                float hp = fmaxf(y1 - y0, 1.f);
                int ylim = (int)(y0 + hp - 1.f);
                const float* ic = imgs + ((size_t)b*3 + c)*HH*WW;
                #pragma unroll
                for (int q = 0; q < 4; q++) {
                    float dd = (float)(wid*4 + q) + 0.5f;
                    float sy = y0 + fminf(fmaxf(dd*hp/(float)SZ - 0.5f, 0.f), hp - 1.f);
                    float fl = floorf(sy);
                    float fy = sy - fl;
                    int j0 = (int)fl;
                    int j1 = min(j0 + 1, ylim);
                    float a00 = ic[j0*WW + ix0];
                    float a01 = ic[j0*WW + ix1];
                    float a10 = ic[j1*WW + ix0];
                    float a11 = ic[j1*WW + ix1];
                    v[q] = a00*(1.f-fy)*(1.f-fx) + a01*(1.f-fy)*fx
                         + a10*fy*(1.f-fx)       + a11*fy*fx;
                    crop_out[(wid*4+q)*SZ + lane] = v[q];
                }
            }

            // masked taps for this lane (edge zeros folded into coefficient)
            float ck[11];
            #pragma unroll
            for (int t = 0; t < 11; t++) {
                int src = lane - 5 + t;
                ck[t] = ((unsigned)src < 32u) ? GK[t] : 0.f;
            }

            // horizontal conv via shuffles -> col-major smem
            #pragma unroll
            for (int q = 0; q < 4; q++) {
                float a = 0.f, bb = 0.f;
                #pragma unroll
                for (int t = 0; t < 11; t++) {
                    float sh = __shfl_sync(0xffffffffu, v[q], (lane - 5 + t) & 31);
                    a  = fmaf(ck[t], sh,    a);
                    bb = fmaf(ck[t], sh*sh, bb);
                }
                t1[lane*PY + (wid*4+q) + 5] = a;
                t2[lane*PY + (wid*4+q) + 5] = bb;
            }
            __syncthreads();

            // vertical conv: streaming accumulators (low register pressure)
            {
                const int x  = tid & 31;
                const int yq = (tid >> 5) << 2;
                const float* c1 = t1 + x*PY + yq;
                const float* c2 = t2 + x*PY + yq;
                float a0=0.f,a1=0.f,a2=0.f,a3=0.f;
                float b0=0.f,b1=0.f,b2=0.f,b3=0.f;
                #pragma unroll
                for (int k2 = 0; k2 < 14; k2++) {
                    float u1 = c1[k2], u2 = c2[k2];
                    if (k2 <= 10)            { a0 = fmaf(GK[k2],   u1, a0); b0 = fmaf(GK[k2],   u2, b0); }
                    if (k2 >= 1 && k2 <= 11) { a1 = fmaf(GK[k2-1], u1, a1); b1 = fmaf(GK[k2-1], u2, b1); }
                    if (k2 >= 2 && k2 <= 12) { a2 = fmaf(GK[k2-2], u1, a2); b2 = fmaf(GK[k2-2], u2, b2); }
                    if (k2 >= 3)             { a3 = fmaf(GK[k2-3], u1, a3); b3 = fmaf(GK[k2-3], u2, b3); }
                }
                mu_out [(yq+0)*SZ + x] = a0;  sig_out[(yq+0)*SZ + x] = b0 - a0*a0;
                mu_out [(yq+1)*SZ + x] = a1;  sig_out[(yq+1)*SZ + x] = b1 - a1*a1;
                mu_out [(yq+2)*SZ + x] = a2;  sig_out[(yq+2)*SZ + x] = b2 - a2*a2;
                mu_out [(yq+3)*SZ + x] = a3;  sig_out[(yq+3)*SZ + x] = b3 - a3*a3;
            }
            __threadfence();
            __syncthreads();
            if (tid == 0) d_ready[it] = 1;
            // no trailing sync needed: flag store is independent of smem;
            // next item's smem writes precede a __syncthreads before any read.
        }
    }

    // ================= PHASE 2: pairs ======================================
    if (tid == 0) { spin_flag(&d_valid_ready); __threadfence(); }
    __syncthreads();
    const int nitems = d_valid_cnt * 3;

    for (int itp = bid; itp < nitems; itp += GRID) {
        const int v = itp / 3;
        const int c = itp - v*3;
        const int pair = d_valid_idx[v];
        const int b = pair >> 10, r = pair & 1023, i = r >> 6, j = r & 63;

        if (tid == 0) {
            spin_flag(&d_ready[b*(NBOX*3) + i*3 + c]);
            spin_flag(&d_ready[b*(NBOX*3) + (NG + j)*3 + c]);
            __threadfence();
        }
        __syncthreads();

        const float* gbase = d_gcrop + ((size_t)(b*NG + i)*3 + c)*NPIX;
        const float* pbase = d_pcrop + ((size_t)(b*NP + j)*3 + c)*NPIX;
        const float* mug   = d_mug   + ((size_t)(b*NG + i)*3 + c)*NPIX;
        const float* sigg  = d_sigg  + ((size_t)(b*NG + i)*3 + c)*NPIX;
        const float* mup   = d_mup   + ((size_t)(b*NP + j)*3 + c)*NPIX;
        const float* sigp  = d_sigp  + ((size_t)(b*NP + j)*3 + c)*NPIX;

        float acc_ssim = 0.f, acc_l1 = 0.f;

        // load g,p rows (coalesced), product in registers, L1 accumulate
        float gp[4];
        #pragma unroll
        for (int q = 0; q < 4; q++) {
            const int p = (wid*4+q)*SZ + lane;
            float gv = gbase[p];
            float pv = pbase[p];
            gp[q] = gv * pv;
            acc_l1 += fabsf(gv - pv) * (1.0f/255.0f);
        }

        // masked taps
        float ck[11];
        #pragma unroll
        for (int t = 0; t < 11; t++) {
            int src = lane - 5 + t;
            ck[t] = ((unsigned)src < 32u) ? GK[t] : 0.f;
        }

        // horizontal conv of product via shuffles
        #pragma unroll
        for (int q = 0; q < 4; q++) {
            float a = 0.f;
            #pragma unroll
            for (int t = 0; t < 11; t++) {
                float sh = __shfl_sync(0xffffffffu, gp[q], (lane - 5 + t) & 31);
                a = fmaf(ck[t], sh, a);
            }
            t1[lane*PY + (wid*4+q) + 5] = a;
        }
        __syncthreads();

        // vertical conv (streaming) + SSIM
        {
            const int x  = tid & 31;
            const int yq = (tid >> 5) << 2;
            const float* c1 = t1 + x*PY + yq;
            float e0=0.f,e1=0.f,e2=0.f,e3=0.f;
            #pragma unroll
            for (int k2 = 0; k2 < 14; k2++) {
                float u = c1[k2];
                if (k2 <= 10)            e0 = fmaf(GK[k2],   u, e0);
                if (k2 >= 1 && k2 <= 11) e1 = fmaf(GK[k2-1], u, e1);
                if (k2 >= 2 && k2 <= 12) e2 = fmaf(GK[k2-2], u, e2);
                if (k2 >= 3)             e3 = fmaf(GK[k2-3], u, e3);
            }
            float egp[4] = {e0, e1, e2, e3};
            #pragma unroll
            for (int q = 0; q < 4; q++) {
                const int p = (yq+q)*SZ + x;
                float mg  = mug [p];
                float mp_ = mup [p];
                float sg  = sigg[p];
                float sp  = sigp[p];
                float sgp = egp[q] - mg*mp_;
                float num = (2.f*mg*mp_ + C1V) * (2.f*sgp + C2V);
                float den = (mg*mg + mp_*mp_ + C1V) * (sg + sp + C2V);
                acc_ssim += num / den;
            }
        }

        #pragma unroll
        for (int o = 16; o > 0; o >>= 1) {
            acc_ssim += __shfl_down_sync(0xffffffffu, acc_ssim, o);
            acc_l1   += __shfl_down_sync(0xffffffffu, acc_l1,   o);
        }
        if (lane == 0) { ws[wid] = acc_ssim; wl[wid] = acc_l1; }
        __syncthreads();
        if (tid == 0) {
            float s = 0.f, l = 0.f;
            #pragma unroll
            for (int w = 0; w < 8; w++) { s += ws[w]; l += wl[w]; }
            d_v_ssim[itp] = s;
            d_v_l1  [itp] = l;
        }
        // no trailing sync: ws/wl rewritten only after the next item's
        // mid-item __syncthreads.
    }

    // ================= PHASE 3: fused finalize ==============================
    __syncthreads();
    if (tid == 0) {
        __threadfence();
        unsigned int t = atomicAdd(&d_done, 1u);
        s_last = (t == GRID - 1u) ? 1 : 0;
    }
    __syncthreads();
    if (!s_last) return;
    __threadfence();

    float* rs = t1;            // reuse smem
    float* rl = t1 + NT;
    float cs = 0.f, cl = 0.f;
    for (int p = tid; p < nitems; p += NT) { cs += d_v_ssim[p]; cl += d_v_l1[p]; }
    rs[tid] = cs; rl[tid] = cl;
    __syncthreads();
    #pragma unroll
    for (int s = NT/2; s > 0; s >>= 1) {
        if (tid < s) { rs[tid] += rs[tid+s]; rl[tid] += rl[tid+s]; }
        __syncthreads();
    }
    for (int p = tid; p < NBOXI; p += NT) d_ready[p] = 0;   // reset for replay
    if (tid == 0) {
        float cnt   = (float)d_valid_cnt;
        float denom = fmaxf(cnt, 1.f) * 3.0f * (float)NPIX;
        float loss  = rl[0] / denom + 1.f - rs[0] / denom;
        out[0] = (cnt > 0.f) ? loss : 0.f;
        d_valid_ready = 0;
        d_done        = 0u;
    }
}

extern "C" void kernel_launch(void* const* d_in, const int* in_sizes, int n_in,
                              void* d_out, int out_size)
{
    const float* imgs = (const float*)d_in[0];   // (4,3,640,640)
    const float* gt   = (const float*)d_in[1];   // (4,16,4)
    const float* pr   = (const float*)d_in[2];   // (4,64,4)
    float* out = (float*)d_out;

    fused_kernel<<<GRID, NT>>>(imgs, gt, pr, out);
}